// round 2
// baseline (speedup 1.0000x reference)
#include <cuda_runtime.h>
#include <cuda_bf16.h>
#include <cstdint>

// Problem constants
#define BB 64
#define PP 196
#define EE 2048
#define LL 32
#define VV 10000
#define EMB 512
#define DEC 512
#define ATT 512
#define TT 31   // L-1 steps

// ---------------- device scratch (no runtime allocation allowed) ----------------
__device__ __align__(16) int   d_sort_src[BB];   // sorted position -> original batch index
__device__ __align__(16) int   d_nb[TT + 1];     // active-row count per timestep
__device__ __align__(16) float d_mean[BB * EE];
__device__ __align__(16) float d_h[BB * DEC];
__device__ __align__(16) float d_c[BB * DEC];
__device__ __align__(16) float d_att1[(size_t)BB * PP * ATT];  // 25.7 MB
__device__ __align__(16) float d_att2[BB * ATT];
__device__ __align__(16) float d_alpha[BB * PP];
__device__ __align__(16) float d_gate[BB * EE];
__device__ __align__(16) float d_xbuf[BB * 3072];  // [emb(512) | gate*awe(2048) | h(512)]
__device__ __align__(16) float d_g[BB * (4 * DEC)];

// Buffer selectors (device-side resolution — NEVER pass __device__ symbols from host!)
#define BUF_MEAN 0
#define BUF_H    1
#define BUF_C    2
#define BUF_ATT2 3
#define BUF_GATE 4
#define BUF_XBUF 5
#define BUF_G    6
#define BUF_EXT  7

__device__ __forceinline__ float* selbuf(int s) {
    switch (s) {
        case BUF_MEAN: return d_mean;
        case BUF_H:    return d_h;
        case BUF_C:    return d_c;
        case BUF_ATT2: return d_att2;
        case BUF_GATE: return d_gate;
        case BUF_XBUF: return d_xbuf;
        case BUF_G:    return d_g;
        default:       return nullptr;
    }
}

// ---------------- setup: stable descending argsort + active counts ----------------
__global__ void k_setup(const int* __restrict__ cap_len) {
    __shared__ int lens[BB];
    int b = threadIdx.x;
    if (b < BB) lens[b] = cap_len[b];  // shape (B,1)
    __syncthreads();
    if (b < BB) {
        int rank = 0;
        int lb = lens[b];
        for (int j = 0; j < BB; j++) {
            int lj = lens[j];
            if (lj > lb || (lj == lb && j < b)) rank++;
        }
        d_sort_src[rank] = b;
    }
    if (b < TT) {
        int cnt = 0;
        for (int j = 0; j < BB; j++) if (lens[j] - 1 > b) cnt++;
        d_nb[b] = cnt;
    }
}

// ---------------- zero the output buffer (harness poisons it) ----------------
__global__ void k_zero(float* __restrict__ out, size_t n) {
    size_t i = (size_t)blockIdx.x * blockDim.x + threadIdx.x;
    size_t stride = (size_t)gridDim.x * blockDim.x;
    for (; i < n; i += stride) out[i] = 0.0f;
}

// ---------------- mean over P (uses sort indirection) ----------------
__global__ void k_mean(const float* __restrict__ enc) {
    int b = blockIdx.y;
    int e = blockIdx.x * 256 + threadIdx.x;
    const float* base = enc + (size_t)d_sort_src[b] * PP * EE + e;
    float s = 0.0f;
    #pragma unroll 7
    for (int p = 0; p < PP; p++) s += base[(size_t)p * EE];
    d_mean[b * EE + e] = s * (1.0f / 196.0f);
}

// ---------------- generic skinny GEMM: Y(64,N) = X(64,K) @ [W1;W2](K,N) + b1 + b2 ----------------
// blockIdx.x -> 16 output columns. 256 threads: 16 col-groups x 16 row-groups (4 rows each).
// Rows >= nb (per-step active count) skip FMAs and stores. act==1 -> sigmoid.
__global__ void k_gemm64(int xsel,
                         const float* __restrict__ W1, const float* __restrict__ W2,
                         int K, int K1,
                         const float* __restrict__ b1, const float* __restrict__ b2,
                         int ysel, float* __restrict__ Yext, long long ldy,
                         int N, int act, int t) {
    const float* X = selbuf(xsel);
    float* Y = (ysel == BUF_EXT) ? Yext : selbuf(ysel);

    __shared__ __align__(16) float Xs[16][68];
    __shared__ float Ws[16][17];
    int tid = threadIdx.x;
    int nl = tid & 15;          // local col
    int mg = tid >> 4;          // 0..15 row group
    int m0 = mg << 2;           // first of 4 rows
    int n0 = blockIdx.x * 16;
    int nb = (t >= 0) ? d_nb[t] : BB;
    bool rowact = (m0 < nb);

    int lm = tid >> 2;          // X-load row 0..63
    int lk = (tid & 3) << 2;    // X-load k offset 0,4,8,12
    int wk = tid >> 4;          // W-load k 0..15
    int wn = tid & 15;          // W-load n

    float a0 = 0.f, a1 = 0.f, a2 = 0.f, a3 = 0.f;
    for (int k0 = 0; k0 < K; k0 += 16) {
        float4 xv = *reinterpret_cast<const float4*>(X + (size_t)lm * K + k0 + lk);
        Xs[lk + 0][lm] = xv.x; Xs[lk + 1][lm] = xv.y;
        Xs[lk + 2][lm] = xv.z; Xs[lk + 3][lm] = xv.w;
        int kg = k0 + wk;
        float wval;
        if (kg < K1) wval = W1[(size_t)kg * N + n0 + wn];
        else         wval = W2[(size_t)(kg - K1) * N + n0 + wn];
        Ws[wk][wn] = wval;
        __syncthreads();
        if (rowact) {
            #pragma unroll
            for (int kk = 0; kk < 16; kk++) {
                float4 x4 = *reinterpret_cast<const float4*>(&Xs[kk][m0]);
                float wv = Ws[kk][nl];
                a0 += x4.x * wv; a1 += x4.y * wv; a2 += x4.z * wv; a3 += x4.w * wv;
            }
        }
        __syncthreads();
    }
    if (!rowact) return;
    int n = n0 + nl;
    float bias = (b1 ? b1[n] : 0.f) + (b2 ? b2[n] : 0.f);
    float r[4] = {a0 + bias, a1 + bias, a2 + bias, a3 + bias};
    #pragma unroll
    for (int j = 0; j < 4; j++) {
        int m = m0 + j;
        if (m < nb) {
            float v = r[j];
            if (act == 1) v = 1.0f / (1.0f + __expf(-v));
            Y[(size_t)m * ldy + n] = v;
        }
    }
}

// ---------------- att1 = enc[sorted] @ We + be : (12544,2048)x(2048,512) ----------------
// 128x64 block tile, 16 k-tile, 256 threads, 8x4 register tile.
__global__ void k_att1(const float* __restrict__ enc, const float* __restrict__ We,
                       const float* __restrict__ be) {
    __shared__ __align__(16) float As[16][136];
    __shared__ __align__(16) float Bs[16][68];
    int tid = threadIdx.x;
    int tn = tid & 15, tm = tid >> 4;
    int n0l = tn * 4;
    int m0l = tm * 8;
    int rowBase = blockIdx.x * 128;
    int colBase = blockIdx.y * 64;

    int lm = tid >> 1;
    int lk = (tid & 1) << 3;
    int r = rowBase + lm;
    int bidx = r / PP, pidx = r % PP;
    const float* Arow = enc + ((size_t)d_sort_src[bidx] * PP + pidx) * EE;

    int bk = tid >> 4, bn = (tid & 15) << 2;

    float acc[8][4];
    #pragma unroll
    for (int i = 0; i < 8; i++)
        #pragma unroll
        for (int j = 0; j < 4; j++) acc[i][j] = 0.f;

    for (int k0 = 0; k0 < EE; k0 += 16) {
        float4 av0 = *reinterpret_cast<const float4*>(Arow + k0 + lk);
        float4 av1 = *reinterpret_cast<const float4*>(Arow + k0 + lk + 4);
        As[lk + 0][lm] = av0.x; As[lk + 1][lm] = av0.y;
        As[lk + 2][lm] = av0.z; As[lk + 3][lm] = av0.w;
        As[lk + 4][lm] = av1.x; As[lk + 5][lm] = av1.y;
        As[lk + 6][lm] = av1.z; As[lk + 7][lm] = av1.w;
        float4 bv = *reinterpret_cast<const float4*>(We + (size_t)(k0 + bk) * ATT + colBase + bn);
        *reinterpret_cast<float4*>(&Bs[bk][bn]) = bv;
        __syncthreads();
        #pragma unroll
        for (int kk = 0; kk < 16; kk++) {
            float4 x0 = *reinterpret_cast<const float4*>(&As[kk][m0l]);
            float4 x1 = *reinterpret_cast<const float4*>(&As[kk][m0l + 4]);
            float4 w  = *reinterpret_cast<const float4*>(&Bs[kk][n0l]);
            float xr[8] = {x0.x, x0.y, x0.z, x0.w, x1.x, x1.y, x1.z, x1.w};
            float wr[4] = {w.x, w.y, w.z, w.w};
            #pragma unroll
            for (int i = 0; i < 8; i++)
                #pragma unroll
                for (int j = 0; j < 4; j++)
                    acc[i][j] += xr[i] * wr[j];
        }
        __syncthreads();
    }
    int c = colBase + n0l;
    #pragma unroll
    for (int i = 0; i < 8; i++) {
        int rr = rowBase + m0l + i;
        float4 o;
        o.x = acc[i][0] + be[c + 0];
        o.y = acc[i][1] + be[c + 1];
        o.z = acc[i][2] + be[c + 2];
        o.w = acc[i][3] + be[c + 3];
        *reinterpret_cast<float4*>(d_att1 + (size_t)rr * ATT + c) = o;
    }
}

// ---------------- e = relu(att1 + att2) @ Wf + bf, then softmax over P ----------------
__global__ void k_esoftmax(const float* __restrict__ Wf, const float* __restrict__ bf,
                           float* __restrict__ out_alphas, int t) {
    int b = blockIdx.x;
    if (b >= d_nb[t]) return;
    __shared__ float a2[ATT];
    __shared__ float es[PP];
    __shared__ float red[8];
    __shared__ float redsum[8];
    int tid = threadIdx.x;
    a2[tid] = d_att2[b * ATT + tid];
    a2[tid + 256] = d_att2[b * ATT + 256 + tid];
    __syncthreads();
    int lane = tid & 31, warp = tid >> 5;
    for (int p = warp; p < PP; p += 8) {
        const float* row = d_att1 + ((size_t)b * PP + p) * ATT;
        float s = 0.f;
        for (int a = lane; a < ATT; a += 32) {
            float v = row[a] + a2[a];
            v = fmaxf(v, 0.f);
            s += v * Wf[a];
        }
        #pragma unroll
        for (int off = 16; off > 0; off >>= 1) s += __shfl_xor_sync(0xffffffffu, s, off);
        if (lane == 0) es[p] = s + bf[0];
    }
    __syncthreads();
    float v = (tid < PP) ? es[tid] : -1e30f;
    float m = v;
    #pragma unroll
    for (int off = 16; off > 0; off >>= 1) m = fmaxf(m, __shfl_xor_sync(0xffffffffu, m, off));
    if (lane == 0) red[warp] = m;
    __syncthreads();
    if (tid == 0) {
        float mm = red[0];
        for (int i = 1; i < 8; i++) mm = fmaxf(mm, red[i]);
        red[0] = mm;
    }
    __syncthreads();
    float smax = red[0];
    float ev = (tid < PP) ? __expf(v - smax) : 0.f;
    float s = ev;
    #pragma unroll
    for (int off = 16; off > 0; off >>= 1) s += __shfl_xor_sync(0xffffffffu, s, off);
    if (lane == 0) redsum[warp] = s;
    __syncthreads();
    if (tid == 0) {
        float ss = redsum[0];
        for (int i = 1; i < 8; i++) ss += redsum[i];
        redsum[0] = ss;
    }
    __syncthreads();
    float inv = 1.0f / redsum[0];
    if (tid < PP) {
        float al = ev * inv;
        d_alpha[b * PP + tid] = al;
        out_alphas[((size_t)b * TT + t) * PP + tid] = al;
    }
}

// ---------------- awe = sum_p alpha*enc ; xbuf = [emb_t | gate*awe | h] ----------------
__global__ void k_awe(const float* __restrict__ enc, const int* __restrict__ caps,
                      const float* __restrict__ emb, int t) {
    int b = blockIdx.y;
    if (b >= d_nb[t]) return;
    int tid = threadIdx.x;
    __shared__ float al[PP];
    if (tid < PP) al[tid] = d_alpha[b * PP + tid];
    __syncthreads();
    int e = blockIdx.x * 256 + tid;
    int src = d_sort_src[b];
    const float* encb = enc + (size_t)src * PP * EE + e;
    float s = 0.f;
    #pragma unroll 7
    for (int p = 0; p < PP; p++) s += al[p] * encb[(size_t)p * EE];
    d_xbuf[b * 3072 + 512 + e] = d_gate[b * EE + e] * s;
    if (blockIdx.x < 2) {  // e in [0,512): fill emb slice and h slice
        int cap = caps[src * LL + t];
        d_xbuf[b * 3072 + e] = emb[(size_t)cap * EMB + e];
        d_xbuf[b * 3072 + 2560 + e] = d_h[b * DEC + e];
    }
}

// ---------------- LSTM cell pointwise: update h,c for active rows ----------------
__global__ void k_lstm(int t) {
    int b = blockIdx.x;
    if (b >= d_nb[t]) return;
    int d = blockIdx.y * 256 + threadIdx.x;
    const float* g = d_g + b * 2048;
    float ig = g[d], fg = g[512 + d], gg = g[1024 + d], og = g[1536 + d];
    float c = d_c[b * DEC + d];
    float si = 1.0f / (1.0f + __expf(-ig));
    float sf = 1.0f / (1.0f + __expf(-fg));
    float so = 1.0f / (1.0f + __expf(-og));
    float cn = sf * c + si * tanhf(gg);
    float hn = so * tanhf(cn);
    d_c[b * DEC + d] = cn;
    d_h[b * DEC + d] = hn;
}

// ---------------- host launch (graph-capturable: default stream, launches only) ----------------
extern "C" void kernel_launch(void* const* d_in, const int* in_sizes, int n_in,
                              void* d_out, int out_size) {
    const float* enc  = (const float*)d_in[0];
    const int*   caps = (const int*)d_in[1];
    const int*   clen = (const int*)d_in[2];
    const float* emb  = (const float*)d_in[3];
    const float* We   = (const float*)d_in[4];
    const float* be   = (const float*)d_in[5];
    const float* Wd   = (const float*)d_in[6];
    const float* bd   = (const float*)d_in[7];
    const float* Wf   = (const float*)d_in[8];
    const float* bf   = (const float*)d_in[9];
    const float* Wih  = (const float*)d_in[10];
    const float* bih  = (const float*)d_in[11];
    const float* Whh  = (const float*)d_in[12];
    const float* bhh  = (const float*)d_in[13];
    const float* Wb   = (const float*)d_in[14];
    const float* bb   = (const float*)d_in[15];
    const float* Whi  = (const float*)d_in[16];
    const float* bhi  = (const float*)d_in[17];
    const float* Wci  = (const float*)d_in[18];
    const float* bci  = (const float*)d_in[19];
    const float* Wfc  = (const float*)d_in[20];
    const float* bfc  = (const float*)d_in[21];
    float* out = (float*)d_out;
    float* out_alphas = out + (size_t)BB * TT * VV;

    k_setup<<<1, 64>>>(clen);
    k_zero<<<2048, 256>>>(out, (size_t)out_size);
    k_mean<<<dim3(8, BB), 256>>>(enc);
    // h0 = mean @ Whi + bhi ; c0 = mean @ Wci + bci
    k_gemm64<<<32, 256>>>(BUF_MEAN, Whi, nullptr, EE, EE, bhi, nullptr,
                          BUF_H, nullptr, DEC, DEC, 0, -1);
    k_gemm64<<<32, 256>>>(BUF_MEAN, Wci, nullptr, EE, EE, bci, nullptr,
                          BUF_C, nullptr, DEC, DEC, 0, -1);
    // att1 = enc @ We + be
    k_att1<<<dim3(98, 8), 256>>>(enc, We, be);

    for (int t = 0; t < TT; t++) {
        // att2 = h @ Wd + bd
        k_gemm64<<<32, 256>>>(BUF_H, Wd, nullptr, DEC, DEC, bd, nullptr,
                              BUF_ATT2, nullptr, ATT, ATT, 0, t);
        // gate = sigmoid(h @ Wb + bb)
        k_gemm64<<<128, 256>>>(BUF_H, Wb, nullptr, DEC, DEC, bb, nullptr,
                               BUF_GATE, nullptr, EE, EE, 1, t);
        // e -> softmax -> alpha (+ alphas output)
        k_esoftmax<<<BB, 256>>>(Wf, bf, out_alphas, t);
        // awe + gate*awe + xbuf assembly
        k_awe<<<dim3(8, BB), 256>>>(enc, caps, emb, t);
        // g = xbuf @ [Wih;Whh] + bih + bhh
        k_gemm64<<<128, 256>>>(BUF_XBUF, Wih, Whh, 3072, 2560, bih, bhh,
                               BUF_G, nullptr, 2048, 2048, 0, t);
        // LSTM cell update (active rows only == mask semantics)
        k_lstm<<<dim3(BB, 2), 256>>>(t);
        // preds = h_new @ Wfc + bfc, written masked & strided into output
        k_gemm64<<<625, 256>>>(BUF_H, Wfc, nullptr, DEC, DEC, bfc, nullptr,
                               BUF_EXT, out + (size_t)t * VV, (long long)TT * VV, VV, 0, t);
    }
}

// round 3
// speedup vs baseline: 1.9443x; 1.9443x over previous
#include <cuda_runtime.h>
#include <cuda_bf16.h>
#include <cstdint>

// Problem constants
#define BB 64
#define PP 196
#define EE 2048
#define LL 32
#define VV 10000
#define EMB 512
#define DEC 512
#define ATT 512
#define TT 31   // L-1 steps

// ---------------- device scratch (no runtime allocation allowed) ----------------
__device__ __align__(16) int   d_sort_src[BB];
__device__ __align__(16) int   d_nb[TT + 1];
__device__ __align__(16) float d_mean[BB * EE];
__device__ __align__(16) float d_h[BB * DEC];
__device__ __align__(16) float d_c[BB * DEC];
__device__ __align__(16) float d_att1[(size_t)BB * PP * ATT];
__device__ __align__(16) float d_att2[BB * ATT];
__device__ __align__(16) float d_alpha[BB * PP];
__device__ __align__(16) float d_gate[BB * EE];
__device__ __align__(16) float d_xbuf[BB * 3072];  // [emb(512) | gate*awe(2048) | h(512)]
__device__ __align__(16) float d_part[8 * BB * 2048];  // split-K partials (max 4x64x2048 / 8x64x512)

// Buffer selectors (device-side resolution — never pass __device__ symbols from host)
#define BUF_MEAN 0
#define BUF_H    1
#define BUF_C    2
#define BUF_XBUF 5
#define BUF_EXT  7

__device__ __forceinline__ float* selbuf(int s) {
    switch (s) {
        case BUF_MEAN: return d_mean;
        case BUF_H:    return d_h;
        case BUF_C:    return d_c;
        case BUF_XBUF: return d_xbuf;
        default:       return nullptr;
    }
}

// gemm modes
#define MODE_DIRECT 0
#define MODE_PART   1
#define MODE_AG     2

// ---------------- setup: stable descending argsort + active counts ----------------
__global__ void k_setup(const int* __restrict__ cap_len) {
    __shared__ int lens[BB];
    int b = threadIdx.x;
    if (b < BB) lens[b] = cap_len[b];
    __syncthreads();
    if (b < BB) {
        int rank = 0;
        int lb = lens[b];
        for (int j = 0; j < BB; j++) {
            int lj = lens[j];
            if (lj > lb || (lj == lb && j < b)) rank++;
        }
        d_sort_src[rank] = b;
    }
    if (b < TT) {
        int cnt = 0;
        for (int j = 0; j < BB; j++) if (lens[j] - 1 > b) cnt++;
        d_nb[b] = cnt;
    }
}

__global__ void k_zero(float* __restrict__ out, size_t n) {
    size_t i = (size_t)blockIdx.x * blockDim.x + threadIdx.x;
    size_t stride = (size_t)gridDim.x * blockDim.x;
    for (; i < n; i += stride) out[i] = 0.0f;
}

__global__ void k_mean(const float* __restrict__ enc) {
    int b = blockIdx.y;
    int e = blockIdx.x * 256 + threadIdx.x;
    const float* base = enc + (size_t)d_sort_src[b] * PP * EE + e;
    float s = 0.0f;
    #pragma unroll 7
    for (int p = 0; p < PP; p++) s += base[(size_t)p * EE];
    d_mean[b * EE + e] = s * (1.0f / 196.0f);
}

// ---------------- W element load (supports row-concat [W1;W2] and N-tail guard) ----------------
__device__ __forceinline__ float wload(const float* __restrict__ W1, const float* __restrict__ W2,
                                       int K1, int Nw, int kg, int n) {
    if (n >= Nw) return 0.0f;
    if (W2 != nullptr && kg >= K1) return W2[(size_t)(kg - K1) * Nw + n];
    return W1[(size_t)kg * Nw + n];
}

// ---------------- double-buffered skinny GEMM: Y(64,N) = X(64,K) @ W(K,N) ----------------
// 64x32 tile per block, 256 threads, 4 rows x 2 cols per thread, k-tile=16,
// register-prefetch double buffering (one __syncthreads per k-tile).
// grid.x = ceil(N/32) tiles (MODE_AG: 16 att2-tiles then 64 gate-tiles),
// grid.y = split-K index (MODE_PART writes d_part, reduced later).
__global__ void k_gemm(int xsel,
                       const float* __restrict__ W1, const float* __restrict__ W2,
                       int K, int K1, int N,
                       const float* __restrict__ b1, const float* __restrict__ b2,
                       int ysel, float* __restrict__ Yext, long long ldy,
                       int act, int t, int S, int mode) {
    __shared__ __align__(16) float Xs[2][16][68];
    __shared__ __align__(16) float Ws[2][16][34];

    const float* X = selbuf(xsel);
    int tid = threadIdx.x;
    int nb = (t >= 0) ? d_nb[t] : BB;

    // output routing
    const float* Wa = W1;
    const float* Wc = W2;          // concat part
    const float* bias1 = b1;
    const float* bias2 = b2;
    float* Y = nullptr;
    long long ldyl = ldy;
    int actl = act, Nw = N, K1l = K1, n0;
    if (mode == MODE_AG) {
        if (blockIdx.x < 16) {  // att2 = h @ Wd + bd
            Y = d_att2; n0 = blockIdx.x * 32; Nw = ATT; actl = 0; ldyl = ATT;
            bias1 = b1; bias2 = nullptr; Wa = W1; Wc = nullptr; K1l = K;
        } else {                // gate = sigmoid(h @ Wb + bb)
            Y = d_gate; n0 = (blockIdx.x - 16) * 32; Nw = EE; actl = 1; ldyl = EE;
            bias1 = b2; bias2 = nullptr; Wa = W2; Wc = nullptr; K1l = K;
        }
    } else {
        Y = (ysel == BUF_EXT) ? Yext : selbuf(ysel);
        n0 = blockIdx.x * 32;
    }

    int s = blockIdx.y;
    int kbeg = s * (K / S);
    int ntiles = (K / S) / 16;

    int nl = tid & 15;         // col-pair index (cols n0+2nl, n0+2nl+1)
    int mg = tid >> 4;
    int m0 = mg << 2;          // 4 rows per thread
    bool rowact = (m0 < nb);

    int lm = tid >> 2, lk = (tid & 3) << 2;  // X tile loads
    int wk = tid >> 4, wn = tid & 15;        // W tile loads
    const float* Xrow = X + (size_t)lm * K;

    float acc[4][2];
    #pragma unroll
    for (int i = 0; i < 4; i++) { acc[i][0] = 0.f; acc[i][1] = 0.f; }

    float4 xr; float wr0, wr1;
    // prologue: tile 0
    {
        int k0 = kbeg;
        xr = *reinterpret_cast<const float4*>(Xrow + k0 + lk);
        int kg = k0 + wk;
        wr0 = wload(Wa, Wc, K1l, Nw, kg, n0 + wn);
        wr1 = wload(Wa, Wc, K1l, Nw, kg, n0 + wn + 16);
    }
    Xs[0][lk + 0][lm] = xr.x; Xs[0][lk + 1][lm] = xr.y;
    Xs[0][lk + 2][lm] = xr.z; Xs[0][lk + 3][lm] = xr.w;
    Ws[0][wk][wn] = wr0; Ws[0][wk][wn + 16] = wr1;
    __syncthreads();

    for (int it = 0; it < ntiles; it++) {
        int cur = it & 1;
        bool more = (it + 1 < ntiles);
        if (more) {
            int k0 = kbeg + (it + 1) * 16;
            xr = *reinterpret_cast<const float4*>(Xrow + k0 + lk);
            int kg = k0 + wk;
            wr0 = wload(Wa, Wc, K1l, Nw, kg, n0 + wn);
            wr1 = wload(Wa, Wc, K1l, Nw, kg, n0 + wn + 16);
        }
        if (rowact) {
            #pragma unroll
            for (int kk = 0; kk < 16; kk++) {
                float4 xv = *reinterpret_cast<const float4*>(&Xs[cur][kk][m0]);
                float2 wv = *reinterpret_cast<const float2*>(&Ws[cur][kk][nl * 2]);
                acc[0][0] += xv.x * wv.x; acc[0][1] += xv.x * wv.y;
                acc[1][0] += xv.y * wv.x; acc[1][1] += xv.y * wv.y;
                acc[2][0] += xv.z * wv.x; acc[2][1] += xv.z * wv.y;
                acc[3][0] += xv.w * wv.x; acc[3][1] += xv.w * wv.y;
            }
        }
        if (more) {
            int nxt = cur ^ 1;
            Xs[nxt][lk + 0][lm] = xr.x; Xs[nxt][lk + 1][lm] = xr.y;
            Xs[nxt][lk + 2][lm] = xr.z; Xs[nxt][lk + 3][lm] = xr.w;
            Ws[nxt][wk][wn] = wr0; Ws[nxt][wk][wn + 16] = wr1;
        }
        __syncthreads();
    }

    if (!rowact) return;
    int na = n0 + nl * 2;

    if (mode == MODE_PART) {
        #pragma unroll
        for (int j = 0; j < 4; j++) {
            int m = m0 + j;
            if (m < nb) {
                size_t base = ((size_t)(s * BB + m)) * Nw + na;
                d_part[base] = acc[j][0];
                d_part[base + 1] = acc[j][1];
            }
        }
    } else {
        float b0v = 0.f, b1v = 0.f;
        if (na < Nw)     b0v = (bias1 ? bias1[na] : 0.f) + (bias2 ? bias2[na] : 0.f);
        if (na + 1 < Nw) b1v = (bias1 ? bias1[na + 1] : 0.f) + (bias2 ? bias2[na + 1] : 0.f);
        #pragma unroll
        for (int j = 0; j < 4; j++) {
            int m = m0 + j;
            if (m < nb) {
                float v0 = acc[j][0] + b0v;
                float v1 = acc[j][1] + b1v;
                if (actl == 1) {
                    v0 = 1.0f / (1.0f + __expf(-v0));
                    v1 = 1.0f / (1.0f + __expf(-v1));
                }
                if (na < Nw)     Y[(size_t)m * ldyl + na] = v0;
                if (na + 1 < Nw) Y[(size_t)m * ldyl + na + 1] = v1;
            }
        }
    }
}

// ---------------- reduce split-K partials (generic, for h0/c0) ----------------
__global__ void k_reduce(int N, int S, const float* __restrict__ b1, int ysel, int t) {
    int idx = blockIdx.x * 256 + threadIdx.x;
    if (idx >= BB * N) return;
    int m = idx / N, n = idx - m * N;
    int nb = (t >= 0) ? d_nb[t] : BB;
    if (m >= nb) return;
    float v = b1 ? b1[n] : 0.f;
    for (int s = 0; s < S; s++) v += d_part[((size_t)(s * BB + m)) * N + n];
    selbuf(ysel)[(size_t)m * N + n] = v;
}

// ---------------- reduce g partials (S=4, N=2048) + fused LSTM pointwise ----------------
__global__ void k_reduce_lstm(const float* __restrict__ bih, const float* __restrict__ bhh, int t) {
    int idx = blockIdx.x * 256 + threadIdx.x;  // 0 .. 64*512-1
    int b = idx >> 9, d = idx & 511;
    if (b >= d_nb[t]) return;
    float gi = bih[d] + bhh[d];
    float gf = bih[512 + d] + bhh[512 + d];
    float gg = bih[1024 + d] + bhh[1024 + d];
    float go = bih[1536 + d] + bhh[1536 + d];
    #pragma unroll
    for (int s = 0; s < 4; s++) {
        const float* p = d_part + ((size_t)(s * BB + b)) * 2048;
        gi += p[d]; gf += p[512 + d]; gg += p[1024 + d]; go += p[1536 + d];
    }
    float c = d_c[b * DEC + d];
    float si = 1.0f / (1.0f + __expf(-gi));
    float sf = 1.0f / (1.0f + __expf(-gf));
    float so = 1.0f / (1.0f + __expf(-go));
    float cn = sf * c + si * tanhf(gg);
    float hn = so * tanhf(cn);
    d_c[b * DEC + d] = cn;
    d_h[b * DEC + d] = hn;
}

// ---------------- att1 = enc[sorted] @ We + be : (12544,2048)x(2048,512) ----------------
__global__ void k_att1(const float* __restrict__ enc, const float* __restrict__ We,
                       const float* __restrict__ be) {
    __shared__ __align__(16) float As[16][136];
    __shared__ __align__(16) float Bs[16][68];
    int tid = threadIdx.x;
    int tn = tid & 15, tm = tid >> 4;
    int n0l = tn * 4;
    int m0l = tm * 8;
    int rowBase = blockIdx.x * 128;
    int colBase = blockIdx.y * 64;

    int lm = tid >> 1;
    int lk = (tid & 1) << 3;
    int r = rowBase + lm;
    int bidx = r / PP, pidx = r % PP;
    const float* Arow = enc + ((size_t)d_sort_src[bidx] * PP + pidx) * EE;

    int bk = tid >> 4, bn = (tid & 15) << 2;

    float acc[8][4];
    #pragma unroll
    for (int i = 0; i < 8; i++)
        #pragma unroll
        for (int j = 0; j < 4; j++) acc[i][j] = 0.f;

    for (int k0 = 0; k0 < EE; k0 += 16) {
        float4 av0 = *reinterpret_cast<const float4*>(Arow + k0 + lk);
        float4 av1 = *reinterpret_cast<const float4*>(Arow + k0 + lk + 4);
        As[lk + 0][lm] = av0.x; As[lk + 1][lm] = av0.y;
        As[lk + 2][lm] = av0.z; As[lk + 3][lm] = av0.w;
        As[lk + 4][lm] = av1.x; As[lk + 5][lm] = av1.y;
        As[lk + 6][lm] = av1.z; As[lk + 7][lm] = av1.w;
        float4 bv = *reinterpret_cast<const float4*>(We + (size_t)(k0 + bk) * ATT + colBase + bn);
        *reinterpret_cast<float4*>(&Bs[bk][bn]) = bv;
        __syncthreads();
        #pragma unroll
        for (int kk = 0; kk < 16; kk++) {
            float4 x0 = *reinterpret_cast<const float4*>(&As[kk][m0l]);
            float4 x1 = *reinterpret_cast<const float4*>(&As[kk][m0l + 4]);
            float4 w  = *reinterpret_cast<const float4*>(&Bs[kk][n0l]);
            float xr[8] = {x0.x, x0.y, x0.z, x0.w, x1.x, x1.y, x1.z, x1.w};
            float wr[4] = {w.x, w.y, w.z, w.w};
            #pragma unroll
            for (int i = 0; i < 8; i++)
                #pragma unroll
                for (int j = 0; j < 4; j++)
                    acc[i][j] += xr[i] * wr[j];
        }
        __syncthreads();
    }
    int c = colBase + n0l;
    #pragma unroll
    for (int i = 0; i < 8; i++) {
        int rr = rowBase + m0l + i;
        float4 o;
        o.x = acc[i][0] + be[c + 0];
        o.y = acc[i][1] + be[c + 1];
        o.z = acc[i][2] + be[c + 2];
        o.w = acc[i][3] + be[c + 3];
        *reinterpret_cast<float4*>(d_att1 + (size_t)rr * ATT + c) = o;
    }
}

// ---------------- e = relu(att1 + att2) @ Wf + bf, then softmax over P ----------------
__global__ void k_esoftmax(const float* __restrict__ Wf, const float* __restrict__ bf,
                           float* __restrict__ out_alphas, int t) {
    int b = blockIdx.x;
    if (b >= d_nb[t]) return;
    __shared__ float a2[ATT];
    __shared__ float es[PP];
    __shared__ float red[8];
    __shared__ float redsum[8];
    int tid = threadIdx.x;
    a2[tid] = d_att2[b * ATT + tid];
    a2[tid + 256] = d_att2[b * ATT + 256 + tid];
    __syncthreads();
    int lane = tid & 31, warp = tid >> 5;
    for (int p = warp; p < PP; p += 8) {
        const float* row = d_att1 + ((size_t)b * PP + p) * ATT;
        float s = 0.f;
        for (int a = lane; a < ATT; a += 32) {
            float v = row[a] + a2[a];
            v = fmaxf(v, 0.f);
            s += v * Wf[a];
        }
        #pragma unroll
        for (int off = 16; off > 0; off >>= 1) s += __shfl_xor_sync(0xffffffffu, s, off);
        if (lane == 0) es[p] = s + bf[0];
    }
    __syncthreads();
    float v = (tid < PP) ? es[tid] : -1e30f;
    float m = v;
    #pragma unroll
    for (int off = 16; off > 0; off >>= 1) m = fmaxf(m, __shfl_xor_sync(0xffffffffu, m, off));
    if (lane == 0) red[warp] = m;
    __syncthreads();
    if (tid == 0) {
        float mm = red[0];
        for (int i = 1; i < 8; i++) mm = fmaxf(mm, red[i]);
        red[0] = mm;
    }
    __syncthreads();
    float smax = red[0];
    float ev = (tid < PP) ? __expf(v - smax) : 0.f;
    float s = ev;
    #pragma unroll
    for (int off = 16; off > 0; off >>= 1) s += __shfl_xor_sync(0xffffffffu, s, off);
    if (lane == 0) redsum[warp] = s;
    __syncthreads();
    if (tid == 0) {
        float ss = redsum[0];
        for (int i = 1; i < 8; i++) ss += redsum[i];
        redsum[0] = ss;
    }
    __syncthreads();
    float inv = 1.0f / redsum[0];
    if (tid < PP) {
        float al = ev * inv;
        d_alpha[b * PP + tid] = al;
        out_alphas[((size_t)b * TT + t) * PP + tid] = al;
    }
}

// ---------------- awe = sum_p alpha*enc ; xbuf = [emb_t | gate*awe | h] ----------------
__global__ void k_awe(const float* __restrict__ enc, const int* __restrict__ caps,
                      const float* __restrict__ emb, int t) {
    int b = blockIdx.y;
    if (b >= d_nb[t]) return;
    int tid = threadIdx.x;
    __shared__ float al[PP];
    if (tid < PP) al[tid] = d_alpha[b * PP + tid];
    __syncthreads();
    int e = blockIdx.x * 256 + tid;
    int src = d_sort_src[b];
    const float* encb = enc + (size_t)src * PP * EE + e;
    float s = 0.f;
    #pragma unroll 7
    for (int p = 0; p < PP; p++) s += al[p] * encb[(size_t)p * EE];
    d_xbuf[b * 3072 + 512 + e] = d_gate[b * EE + e] * s;
    if (blockIdx.x < 2) {
        int cap = caps[src * LL + t];
        d_xbuf[b * 3072 + e] = emb[(size_t)cap * EMB + e];
        d_xbuf[b * 3072 + 2560 + e] = d_h[b * DEC + e];
    }
}

// ---------------- host launch (graph-capturable) ----------------
extern "C" void kernel_launch(void* const* d_in, const int* in_sizes, int n_in,
                              void* d_out, int out_size) {
    const float* enc  = (const float*)d_in[0];
    const int*   caps = (const int*)d_in[1];
    const int*   clen = (const int*)d_in[2];
    const float* emb  = (const float*)d_in[3];
    const float* We   = (const float*)d_in[4];
    const float* be   = (const float*)d_in[5];
    const float* Wd   = (const float*)d_in[6];
    const float* bd   = (const float*)d_in[7];
    const float* Wf   = (const float*)d_in[8];
    const float* bf   = (const float*)d_in[9];
    const float* Wih  = (const float*)d_in[10];
    const float* bih  = (const float*)d_in[11];
    const float* Whh  = (const float*)d_in[12];
    const float* bhh  = (const float*)d_in[13];
    const float* Wb   = (const float*)d_in[14];
    const float* bb   = (const float*)d_in[15];
    const float* Whi  = (const float*)d_in[16];
    const float* bhi  = (const float*)d_in[17];
    const float* Wci  = (const float*)d_in[18];
    const float* bci  = (const float*)d_in[19];
    const float* Wfc  = (const float*)d_in[20];
    const float* bfc  = (const float*)d_in[21];
    float* out = (float*)d_out;
    float* out_alphas = out + (size_t)BB * TT * VV;

    k_setup<<<1, 64>>>(clen);
    k_zero<<<2048, 256>>>(out, (size_t)out_size);
    k_mean<<<dim3(8, BB), 256>>>(enc);

    // h0 = mean @ Whi + bhi (split-K 8), c0 = mean @ Wci + bci
    k_gemm<<<dim3(16, 8), 256>>>(BUF_MEAN, Whi, nullptr, EE, EE, DEC,
                                 nullptr, nullptr, 0, nullptr, 0, 0, -1, 8, MODE_PART);
    k_reduce<<<128, 256>>>(DEC, 8, bhi, BUF_H, -1);
    k_gemm<<<dim3(16, 8), 256>>>(BUF_MEAN, Wci, nullptr, EE, EE, DEC,
                                 nullptr, nullptr, 0, nullptr, 0, 0, -1, 8, MODE_PART);
    k_reduce<<<128, 256>>>(DEC, 8, bci, BUF_C, -1);

    // att1 = enc @ We + be
    k_att1<<<dim3(98, 8), 256>>>(enc, We, be);

    for (int t = 0; t < TT; t++) {
        // fused: att2 = h@Wd+bd (blocks 0-15), gate = sigmoid(h@Wb+bb) (blocks 16-79)
        k_gemm<<<dim3(80, 1), 256>>>(BUF_H, Wd, Wb, DEC, DEC, EE,
                                     bd, bb, 0, nullptr, 0, 0, t, 1, MODE_AG);
        k_esoftmax<<<BB, 256>>>(Wf, bf, out_alphas, t);
        k_awe<<<dim3(8, BB), 256>>>(enc, caps, emb, t);
        // g partials = xbuf @ [Wih;Whh]  (split-K 4)
        k_gemm<<<dim3(64, 4), 256>>>(BUF_XBUF, Wih, Whh, 3072, 2560, 2048,
                                     nullptr, nullptr, 0, nullptr, 0, 0, t, 4, MODE_PART);
        // reduce + biases + LSTM pointwise -> h, c
        k_reduce_lstm<<<128, 256>>>(bih, bhh, t);
        // preds = h_new @ Wfc + bfc, strided masked write
        k_gemm<<<dim3(313, 1), 256>>>(BUF_H, Wfc, nullptr, DEC, DEC, VV,
                                      bfc, nullptr, BUF_EXT, out + (size_t)t * VV,
                                      (long long)TT * VV, 0, t, 1, MODE_DIRECT);
    }
}